// round 1
// baseline (speedup 1.0000x reference)
#include <cuda_runtime.h>
#include <math.h>
#include <stdint.h>

// Problem constants
#define B_   64
#define S_   256
#define DIM_ 512
#define H_   16
#define DH_  32
// -log2(10000)/32
#define ROPE_COEF (-0.41524101186092147f)

// Scratch: q,k,v in [B,H,S,DH] layout (fp32). 3 x 32MB static device arrays.
__device__ float g_q[B_ * H_ * S_ * DH_];
__device__ float g_k[B_ * H_ * S_ * DH_];
__device__ float g_v[B_ * H_ * S_ * DH_];

// ---------------------------------------------------------------------------
// Kernel 1: QKV projection (SGEMM 128x128x16, 8x8 micro-tile) + bias + RoPE
// C[16384, 1536] = A[16384,512] @ [Wq|Wk|Wv], epilogue writes [B,H,S,DH].
// ---------------------------------------------------------------------------
__global__ __launch_bounds__(256) void qkv_rope_kernel(
    const float* __restrict__ A,
    const float* __restrict__ Wq, const float* __restrict__ bq,
    const float* __restrict__ Wk, const float* __restrict__ bk,
    const float* __restrict__ Wv, const float* __restrict__ bv)
{
    __shared__ float As[16][128];
    __shared__ float Bs[16][128];

    const int tid = threadIdx.x;
    const int tx = tid & 15;
    const int ty = tid >> 4;
    const int bx = blockIdx.x;   // 0..11  (col tile)
    const int by = blockIdx.y;   // 0..127 (row tile)

    const int cg0 = bx * 128;          // global col base (0..1535)
    const int m   = cg0 >> 9;          // 0=Q, 1=K, 2=V
    const float* W    = (m == 0) ? Wq : (m == 1) ? Wk : Wv;
    const float* bias = (m == 0) ? bq : (m == 1) ? bk : bv;
    const int cW0 = cg0 & 511;         // col base within W
    const int r0  = by * 128;

    float acc[8][8];
    #pragma unroll
    for (int i = 0; i < 8; i++)
        #pragma unroll
        for (int j = 0; j < 8; j++) acc[i][j] = 0.0f;

    // A-load mapping: row = tid/2, 8 consecutive k per thread
    const int arow = tid >> 1;
    const int aseg = (tid & 1) << 3;
    // B-load mapping: kk = tid/32 (+8 second pass), float4 col = tid%32
    const int bfc = tid & 31;
    const int bk0 = tid >> 5;

    for (int kt = 0; kt < 512; kt += 16) {
        const float* Ap = A + (size_t)(r0 + arow) * 512 + kt + aseg;
        float4 a04 = *(const float4*)(Ap);
        float4 a14 = *(const float4*)(Ap + 4);
        As[aseg + 0][arow] = a04.x; As[aseg + 1][arow] = a04.y;
        As[aseg + 2][arow] = a04.z; As[aseg + 3][arow] = a04.w;
        As[aseg + 4][arow] = a14.x; As[aseg + 5][arow] = a14.y;
        As[aseg + 6][arow] = a14.z; As[aseg + 7][arow] = a14.w;

        #pragma unroll
        for (int p = 0; p < 2; p++) {
            int kk = bk0 + p * 8;
            float4 w4 = *(const float4*)(W + (size_t)(kt + kk) * 512 + cW0 + (bfc << 2));
            *(float4*)&Bs[kk][bfc << 2] = w4;
        }
        __syncthreads();

        #pragma unroll
        for (int kk = 0; kk < 16; kk++) {
            float4 a0 = *(float4*)&As[kk][ty << 2];
            float4 a1 = *(float4*)&As[kk][64 + (ty << 2)];
            float4 b0 = *(float4*)&Bs[kk][tx << 2];
            float4 b1 = *(float4*)&Bs[kk][64 + (tx << 2)];
            float av[8] = {a0.x, a0.y, a0.z, a0.w, a1.x, a1.y, a1.z, a1.w};
            float bw[8] = {b0.x, b0.y, b0.z, b0.w, b1.x, b1.y, b1.z, b1.w};
            #pragma unroll
            for (int i = 0; i < 8; i++)
                #pragma unroll
                for (int j = 0; j < 8; j++)
                    acc[i][j] += av[i] * bw[j];
        }
        __syncthreads();
    }

    // Epilogue: bias + RoPE (Q,K only), write [B,H,S,DH]
    float* dst = (m == 0) ? g_q : (m == 1) ? g_k : g_v;
    const bool rope = (m < 2);

    #pragma unroll
    for (int jg = 0; jg < 2; jg++) {
        const int cb = cW0 + jg * 64 + (tx << 2);  // multiple of 4
        const int hh = cb >> 5;
        const int d0 = cb & 31;
        const float bi0 = bias[cb + 0], bi1 = bias[cb + 1];
        const float bi2 = bias[cb + 2], bi3 = bias[cb + 3];
        float if0 = 0.f, if1 = 0.f;
        if (rope) {
            if0 = exp2f((float)(d0)     * ROPE_COEF);
            if1 = exp2f((float)(d0 + 2) * ROPE_COEF);
        }
        #pragma unroll
        for (int ig = 0; ig < 2; ig++) {
            #pragma unroll
            for (int i = 0; i < 4; i++) {
                const int r = r0 + ig * 64 + (ty << 2) + i;
                const int b = r >> 8;
                const int s = r & 255;
                float v0 = acc[ig * 4 + i][jg * 4 + 0] + bi0;
                float v1 = acc[ig * 4 + i][jg * 4 + 1] + bi1;
                float v2 = acc[ig * 4 + i][jg * 4 + 2] + bi2;
                float v3 = acc[ig * 4 + i][jg * 4 + 3] + bi3;
                if (rope) {
                    float sn, cs;
                    sincosf((float)s * if0, &sn, &cs);
                    float t0 = v0 * cs - v1 * sn;
                    float t1 = v0 * sn + v1 * cs;
                    sincosf((float)s * if1, &sn, &cs);
                    float t2 = v2 * cs - v3 * sn;
                    float t3 = v2 * sn + v3 * cs;
                    v0 = t0; v1 = t1; v2 = t2; v3 = t3;
                }
                float4 o = make_float4(v0, v1, v2, v3);
                *(float4*)&dst[((size_t)((b * H_ + hh) * S_ + s) << 5) + d0] = o;
            }
        }
    }
}

// ---------------------------------------------------------------------------
// Kernel 2: attention per (b,h). 256 threads.
//   scores[q][k] = (Q K^T)/sqrt(DH); softmax rows; + bias[q-k+255]; @ V.
// ---------------------------------------------------------------------------
#define VS_STRIDE 34
#define PS_STRIDE 264
#define QT_STRIDE 36
#define SMEM_FLOATS (256 * VS_STRIDE + 32 * PS_STRIDE + 32 * QT_STRIDE + 512)

__global__ __launch_bounds__(256) void attn_kernel(
    const float* __restrict__ bias_table, float* __restrict__ out)
{
    extern __shared__ float sm[];
    float* Vs  = sm;                                 // [256][34]
    float* Ps  = Vs + 256 * VS_STRIDE;               // [32][264]
    float* Qt  = Ps + 32 * PS_STRIDE;                // [32][36]
    float* bsm = Qt + 32 * QT_STRIDE;                // [512]

    const int tid = threadIdx.x;
    const int bh = blockIdx.x;
    const int b = bh >> 4;
    const int h = bh & 15;
    const size_t base = (size_t)bh * (S_ * DH_);

    // bias slice for this head
    for (int i = tid; i < 511; i += 256) bsm[i] = bias_table[i * H_ + h];

    // V -> smem [k][d], stride 34
    {
        const float4* Vg = (const float4*)(g_v + base);
        #pragma unroll
        for (int it = 0; it < 8; it++) {
            int f = tid + it * 256;           // 0..2047 float4s
            float4 v4 = Vg[f];
            int k = f >> 3;
            int u = (f & 7) << 2;
            float* p = &Vs[k * VS_STRIDE + u];
            p[0] = v4.x; p[1] = v4.y; p[2] = v4.z; p[3] = v4.w;
        }
    }

    // K row (k = tid) -> registers
    float kreg[32];
    {
        const float4* Kg = (const float4*)(g_k + base + (size_t)tid * DH_);
        #pragma unroll
        for (int u = 0; u < 8; u++) {
            float4 k4 = Kg[u];
            kreg[u * 4 + 0] = k4.x; kreg[u * 4 + 1] = k4.y;
            kreg[u * 4 + 2] = k4.z; kreg[u * 4 + 3] = k4.w;
        }
    }
    __syncthreads();

    const float scale = 0.17677669529663687f;  // 1/sqrt(32)
    const int lane = tid & 31;
    const int warp = tid >> 5;
    const int ty = tid >> 4;   // PV: q pair
    const int tx = tid & 15;   // PV: d pair

    for (int qc = 0; qc < 8; qc++) {
        // Load Q chunk transposed: Qt[d][q]
        #pragma unroll
        for (int it = 0; it < 4; it++) {
            int e = tid + it * 256;          // 0..1023
            int qq = e >> 5, d = e & 31;
            Qt[d * QT_STRIDE + qq] = g_q[base + (size_t)(qc * 32 + qq) * DH_ + d];
        }
        __syncthreads();

        // Scores: thread tid = k index, 32 q's
        {
            float acc[32];
            #pragma unroll
            for (int q = 0; q < 32; q++) acc[q] = 0.0f;
            #pragma unroll
            for (int d = 0; d < 32; d++) {
                const float kv = kreg[d];
                const float4* Qr = (const float4*)&Qt[d * QT_STRIDE];
                #pragma unroll
                for (int q4 = 0; q4 < 8; q4++) {
                    float4 qv = Qr[q4];
                    acc[q4 * 4 + 0] += kv * qv.x;
                    acc[q4 * 4 + 1] += kv * qv.y;
                    acc[q4 * 4 + 2] += kv * qv.z;
                    acc[q4 * 4 + 3] += kv * qv.w;
                }
            }
            #pragma unroll
            for (int q = 0; q < 32; q++)
                Ps[q * PS_STRIDE + tid] = acc[q] * scale;
        }
        __syncthreads();

        // Softmax per q-row (8 warps x 4 rows), in place, + bias
        #pragma unroll
        for (int j = 0; j < 4; j++) {
            const int q = warp * 4 + j;
            const int qg = qc * 32 + q;
            float v[8];
            float mx = -1e30f;
            #pragma unroll
            for (int jj = 0; jj < 8; jj++) {
                v[jj] = Ps[q * PS_STRIDE + lane + jj * 32];
                mx = fmaxf(mx, v[jj]);
            }
            #pragma unroll
            for (int o = 16; o; o >>= 1) mx = fmaxf(mx, __shfl_xor_sync(0xffffffffu, mx, o));
            float sum = 0.0f;
            #pragma unroll
            for (int jj = 0; jj < 8; jj++) { v[jj] = expf(v[jj] - mx); sum += v[jj]; }
            #pragma unroll
            for (int o = 16; o; o >>= 1) sum += __shfl_xor_sync(0xffffffffu, sum, o);
            const float inv = 1.0f / sum;
            #pragma unroll
            for (int jj = 0; jj < 8; jj++) {
                const int k = lane + jj * 32;
                Ps[q * PS_STRIDE + k] = v[jj] * inv + bsm[qg - k + 255];
            }
        }
        __syncthreads();

        // PV: ctx[q][d], thread computes 2x2 (q = 2*ty+{0,1}, d = 2*tx+{0,1})
        {
            float a00 = 0.f, a01 = 0.f, a10 = 0.f, a11 = 0.f;
            const float4* P0 = (const float4*)&Ps[(ty * 2 + 0) * PS_STRIDE];
            const float4* P1 = (const float4*)&Ps[(ty * 2 + 1) * PS_STRIDE];
            #pragma unroll
            for (int k4 = 0; k4 < 64; k4++) {
                float4 p0 = P0[k4];
                float4 p1 = P1[k4];
                const int k = k4 * 4;
                float2 w0 = *(const float2*)&Vs[(k + 0) * VS_STRIDE + tx * 2];
                float2 w1 = *(const float2*)&Vs[(k + 1) * VS_STRIDE + tx * 2];
                float2 w2 = *(const float2*)&Vs[(k + 2) * VS_STRIDE + tx * 2];
                float2 w3 = *(const float2*)&Vs[(k + 3) * VS_STRIDE + tx * 2];
                a00 += p0.x * w0.x; a01 += p0.x * w0.y; a10 += p1.x * w0.x; a11 += p1.x * w0.y;
                a00 += p0.y * w1.x; a01 += p0.y * w1.y; a10 += p1.y * w1.x; a11 += p1.y * w1.y;
                a00 += p0.z * w2.x; a01 += p0.z * w2.y; a10 += p1.z * w2.x; a11 += p1.z * w2.y;
                a00 += p0.w * w3.x; a01 += p0.w * w3.y; a10 += p1.w * w3.x; a11 += p1.w * w3.y;
            }
            const int qg = qc * 32 + ty * 2;
            float* o0 = &out[(size_t)(b * S_ + qg) * DIM_ + h * DH_ + tx * 2];
            *(float2*)o0          = make_float2(a00, a01);
            *(float2*)(o0 + DIM_) = make_float2(a10, a11);
        }
        __syncthreads();
    }
}

// ---------------------------------------------------------------------------
extern "C" void kernel_launch(void* const* d_in, const int* in_sizes, int n_in,
                              void* d_out, int out_size)
{
    const float* hs = (const float*)d_in[0];
    const float* Wq = (const float*)d_in[1];
    const float* bq = (const float*)d_in[2];
    const float* Wk = (const float*)d_in[3];
    const float* bk = (const float*)d_in[4];
    const float* Wv = (const float*)d_in[5];
    const float* bv = (const float*)d_in[6];
    const float* bias_table = (const float*)d_in[7];
    float* out = (float*)d_out;

    (void)in_sizes; (void)n_in; (void)out_size;

    cudaFuncSetAttribute(attn_kernel, cudaFuncAttributeMaxDynamicSharedMemorySize,
                         SMEM_FLOATS * (int)sizeof(float));

    dim3 g1(12, 128);
    qkv_rope_kernel<<<g1, 256>>>(hs, Wq, bq, Wk, bk, Wv, bv);

    attn_kernel<<<B_ * H_, 256, SMEM_FLOATS * sizeof(float)>>>(bias_table, out);
}

// round 8
// speedup vs baseline: 1.4054x; 1.4054x over previous
#include <cuda_runtime.h>
#include <cuda_bf16.h>
#include <math.h>
#include <stdint.h>

// Problem constants
#define B_   64
#define S_   256
#define DIM_ 512
#define H_   16
#define DH_  32
// -log2(10000)/32
#define ROPE_COEF (-0.41524101186092147f)

// ---------------------------------------------------------------------------
// Warp-level MMA helpers (sm_80+ features only; safe on target sm_103)
// ---------------------------------------------------------------------------
__device__ __forceinline__ uint32_t smem_to_u32(const void* smem_ptr) {
    uint32_t addr;
    asm("{ .reg .u64 tmp; cvta.to.shared.u64 tmp, %1; cvt.u32.u64 %0, tmp; }"
        : "=r"(addr) : "l"(smem_ptr));
    return addr;
}

__device__ __forceinline__ void ldm_x4(uint32_t* r, uint32_t addr) {
    asm volatile("ldmatrix.sync.aligned.m8n8.x4.shared.b16 {%0,%1,%2,%3}, [%4];"
                 : "=r"(r[0]), "=r"(r[1]), "=r"(r[2]), "=r"(r[3]) : "r"(addr));
}

__device__ __forceinline__ void mma16816(float* c, const uint32_t* a, const uint32_t* b) {
    asm volatile(
        "mma.sync.aligned.m16n8k16.row.col.f32.bf16.bf16.f32 "
        "{%0,%1,%2,%3}, {%4,%5,%6,%7}, {%8,%9}, {%0,%1,%2,%3};"
        : "+f"(c[0]), "+f"(c[1]), "+f"(c[2]), "+f"(c[3])
        : "r"(a[0]), "r"(a[1]), "r"(a[2]), "r"(a[3]), "r"(b[0]), "r"(b[1]));
}

// ---------------------------------------------------------------------------
// Scratch
// ---------------------------------------------------------------------------
__device__ float g_q[B_ * H_ * S_ * DH_];
__device__ float g_k[B_ * H_ * S_ * DH_];
__device__ float g_v[B_ * H_ * S_ * DH_];

// bf16 split of A (hidden states) [16384, 512]
__device__ __nv_bfloat16 g_ah[16384 * 512];
__device__ __nv_bfloat16 g_al[16384 * 512];
// bf16 split of W^T, all 3 matrices concatenated: rows = mat*512 + n, cols = k
__device__ __nv_bfloat16 g_wh[1536 * 512];
__device__ __nv_bfloat16 g_wl[1536 * 512];

// ---------------------------------------------------------------------------
// Prep A: fp32 -> bf16 hi/lo split
// ---------------------------------------------------------------------------
__global__ __launch_bounds__(256) void prep_a_kernel(const float* __restrict__ hs) {
    size_t i = (size_t)blockIdx.x * 256 + threadIdx.x;   // float4 index
    float4 x = ((const float4*)hs)[i];
    __nv_bfloat16 h0 = __float2bfloat16(x.x);
    __nv_bfloat16 h1 = __float2bfloat16(x.y);
    __nv_bfloat16 h2 = __float2bfloat16(x.z);
    __nv_bfloat16 h3 = __float2bfloat16(x.w);
    __nv_bfloat16 l0 = __float2bfloat16(x.x - __bfloat162float(h0));
    __nv_bfloat16 l1 = __float2bfloat16(x.y - __bfloat162float(h1));
    __nv_bfloat16 l2 = __float2bfloat16(x.z - __bfloat162float(h2));
    __nv_bfloat16 l3 = __float2bfloat16(x.w - __bfloat162float(h3));
    __nv_bfloat162* AH2 = (__nv_bfloat162*)g_ah;
    __nv_bfloat162* AL2 = (__nv_bfloat162*)g_al;
    AH2[2 * i]     = __halves2bfloat162(h0, h1);
    AH2[2 * i + 1] = __halves2bfloat162(h2, h3);
    AL2[2 * i]     = __halves2bfloat162(l0, l1);
    AL2[2 * i + 1] = __halves2bfloat162(l2, l3);
}

// ---------------------------------------------------------------------------
// Prep W: transpose + bf16 hi/lo split.  WT[mat*512 + n][k] = W_mat[k][n]
// ---------------------------------------------------------------------------
__global__ __launch_bounds__(256) void prep_w_kernel(
    const float* __restrict__ Wq, const float* __restrict__ Wk, const float* __restrict__ Wv)
{
    __shared__ float t[32][33];
    const int tid = threadIdx.x;
    const int tx = tid & 31, ty = tid >> 5;
    const int mat = blockIdx.z;
    const float* W = (mat == 0) ? Wq : (mat == 1) ? Wk : Wv;
    const int n0 = blockIdx.x * 32, k0 = blockIdx.y * 32;

    #pragma unroll
    for (int j = 0; j < 4; j++) {
        int kk = ty + j * 8;
        t[kk][tx] = W[(size_t)(k0 + kk) * 512 + n0 + tx];
    }
    __syncthreads();
    #pragma unroll
    for (int j = 0; j < 4; j++) {
        int n = n0 + ty + j * 8;
        float v = t[tx][ty + j * 8];
        __nv_bfloat16 hi = __float2bfloat16(v);
        __nv_bfloat16 lo = __float2bfloat16(v - __bfloat162float(hi));
        size_t o = (size_t)(mat * 512 + n) * 512 + k0 + tx;
        g_wh[o] = hi;
        g_wl[o] = lo;
    }
}

// ---------------------------------------------------------------------------
// QKV GEMM via mma.sync bf16 (3-product hi/lo split) + bias + RoPE epilogue.
// grid (24, 128): bx -> 64-col N tile over [Wq|Wk|Wv], by -> 128-row M tile.
// 256 threads = 8 warps, 4(M) x 2(N); warp tile 32x32; KC=32, double buffer.
// smem rows padded to 40 bf16 (80B, odd 16B-stride) -> conflict-free ldmatrix.
// ---------------------------------------------------------------------------
#define QS_AH   0
#define QS_AL   10240
#define QS_BH   20480
#define QS_BL   25600
#define QS_BUF  30720
#define QS_TOTAL (2 * QS_BUF)   // 61440 bytes

__global__ __launch_bounds__(256) void qkv_mma_kernel(
    const float* __restrict__ bq, const float* __restrict__ bk, const float* __restrict__ bv)
{
    extern __shared__ char smem[];
    const uint32_t sb = smem_to_u32(smem);
    const int tid  = threadIdx.x;
    const int lane = tid & 31;
    const int warp = tid >> 5;
    const int wm = warp & 3;          // 0..3  (M)
    const int wn = warp >> 2;         // 0..1  (N)
    const int nbase = blockIdx.x * 64;     // 0..1472
    const int r0    = blockIdx.y * 128;
    const int mat   = nbase >> 9;
    const bool rope = (mat < 2);

    float acc[2][4][4];
    #pragma unroll
    for (int i = 0; i < 2; i++)
        #pragma unroll
        for (int j = 0; j < 4; j++)
            #pragma unroll
            for (int k = 0; k < 4; k++) acc[i][j][k] = 0.0f;

    // global load mapping: 256 threads; row = tid/4, seg = (tid%4)*8 bf16
    const int grow = tid >> 2;            // 0..63
    const int gseg = (tid & 3) << 3;      // 0,8,16,24
    const size_t aSrc0 = (size_t)(r0 + grow) * 512 + gseg;
    const size_t aSrc1 = aSrc0 + (size_t)64 * 512;
    const size_t bSrc  = (size_t)(nbase + grow) * 512 + gseg;
    const uint32_t aDst0 = (uint32_t)(grow * 40 + gseg) * 2;
    const uint32_t aDst1 = (uint32_t)((grow + 64) * 40 + gseg) * 2;
    const uint32_t bDst  = aDst0;

    // ldmatrix element offsets (per thread, in bf16 elems; ks adds 16)
    const uint32_t aLdmRow = (uint32_t)(lane & 15);
    const uint32_t aLdmCol = (uint32_t)((lane >> 4) << 3);
    const uint32_t bLdmRow = (uint32_t)((lane & 7) + (((lane >> 4) & 1) << 3));
    const uint32_t bLdmCol = (uint32_t)(((lane >> 3) & 1) << 3);

    // preload chunk 0 into buffer 0
    {
        *(uint4*)(smem + QS_AH + aDst0) = *(const uint4*)&g_ah[aSrc0];
        *(uint4*)(smem + QS_AL + aDst0) = *(const uint4*)&g_al[aSrc0];
        *(uint4*)(smem + QS_AH + aDst1) = *(const uint4*)&g_ah[aSrc1];
        *(uint4*)(smem + QS_AL + aDst1) = *(const uint4*)&g_al[aSrc1];
        *(uint4*)(smem + QS_BH + bDst)  = *(const uint4*)&g_wh[bSrc];
        *(uint4*)(smem + QS_BL + bDst)  = *(const uint4*)&g_wl[bSrc];
    }
    __syncthreads();

    for (int c = 0; c < 16; c++) {
        uint4 pAh0, pAl0, pAh1, pAl1, pBh, pBl;
        if (c < 15) {
            const int kn = (c + 1) * 32;
            pAh0 = *(const uint4*)&g_ah[aSrc0 + kn];
            pAl0 = *(const uint4*)&g_al[aSrc0 + kn];
            pAh1 = *(const uint4*)&g_ah[aSrc1 + kn];
            pAl1 = *(const uint4*)&g_al[aSrc1 + kn];
            pBh  = *(const uint4*)&g_wh[bSrc + kn];
            pBl  = *(const uint4*)&g_wl[bSrc + kn];
        }

        const uint32_t bb = sb + (uint32_t)(c & 1) * QS_BUF;
        #pragma unroll
        for (int ks = 0; ks < 2; ks++) {
            uint32_t Ah[2][4], Al[2][4], Bh[2][4], Bl[2][4];
            #pragma unroll
            for (int mt = 0; mt < 2; mt++) {
                uint32_t eo = ((uint32_t)(wm * 32 + mt * 16) + aLdmRow) * 40
                              + (uint32_t)(ks * 16) + aLdmCol;
                ldm_x4(Ah[mt], bb + QS_AH + eo * 2);
                ldm_x4(Al[mt], bb + QS_AL + eo * 2);
            }
            #pragma unroll
            for (int p = 0; p < 2; p++) {
                uint32_t eo = ((uint32_t)(wn * 32 + p * 16) + bLdmRow) * 40
                              + (uint32_t)(ks * 16) + bLdmCol;
                ldm_x4(Bh[p], bb + QS_BH + eo * 2);
                ldm_x4(Bl[p], bb + QS_BL + eo * 2);
            }
            #pragma unroll
            for (int mt = 0; mt < 2; mt++)
                #pragma unroll
                for (int nt = 0; nt < 4; nt++) {
                    const uint32_t* bhp = &Bh[nt >> 1][(nt & 1) * 2];
                    const uint32_t* blp = &Bl[nt >> 1][(nt & 1) * 2];
                    mma16816(acc[mt][nt], Ah[mt], bhp);
                    mma16816(acc[mt][nt], Ah[mt], blp);
                    mma16816(acc[mt][nt], Al[mt], bhp);
                }
        }

        if (c < 15) {
            char* nb = smem + (size_t)((c + 1) & 1) * QS_BUF;
            *(uint4*)(nb + QS_AH + aDst0) = pAh0;
            *(uint4*)(nb + QS_AL + aDst0) = pAl0;
            *(uint4*)(nb + QS_AH + aDst1) = pAh1;
            *(uint4*)(nb + QS_AL + aDst1) = pAl1;
            *(uint4*)(nb + QS_BH + bDst)  = pBh;
            *(uint4*)(nb + QS_BL + bDst)  = pBl;
            __syncthreads();
        }
    }

    // Epilogue: bias + RoPE, write [B,H,S,DH] fp32
    const float* bias = (mat == 0) ? bq : (mat == 1) ? bk : bv;
    float* dst = (mat == 0) ? g_q : (mat == 1) ? g_k : g_v;

    #pragma unroll
    for (int nt = 0; nt < 4; nt++) {
        const int cg = nbase + wn * 32 + nt * 8 + (lane & 3) * 2;  // global col
        const int cW = cg & 511;
        const int head = cW >> 5;
        const int d0 = cW & 31;                                    // even
        const float bi0 = bias[cW];
        const float bi1 = bias[cW + 1];
        const float ifr = rope ? exp2f((float)d0 * ROPE_COEF) : 0.0f;
        #pragma unroll
        for (int mt = 0; mt < 2; mt++) {
            const int rbase = r0 + wm * 32 + mt * 16 + (lane >> 2);
            #pragma unroll
            for (int half = 0; half < 2; half++) {
                const int r = rbase + half * 8;
                const int b = r >> 8;
                const int s = r & 255;
                float v0 = acc[mt][nt][half * 2 + 0] + bi0;
                float v1 = acc[mt][nt][half * 2 + 1] + bi1;
                if (rope) {
                    float sn, cs;
                    sincosf((float)s * ifr, &sn, &cs);
                    float t0 = v0 * cs - v1 * sn;
                    float t1 = v0 * sn + v1 * cs;
                    v0 = t0; v1 = t1;
                }
                *(float2*)&dst[((size_t)((b * H_ + head) * S_ + s) << 5) + d0] =
                    make_float2(v0, v1);
            }
        }
    }
}

// ---------------------------------------------------------------------------
// Kernel 2: attention per (b,h). Unchanged from R1.
// ---------------------------------------------------------------------------
#define VS_STRIDE 34
#define PS_STRIDE 264
#define QT_STRIDE 36
#define SMEM_FLOATS (256 * VS_STRIDE + 32 * PS_STRIDE + 32 * QT_STRIDE + 512)

__global__ __launch_bounds__(256) void attn_kernel(
    const float* __restrict__ bias_table, float* __restrict__ out)
{
    extern __shared__ float sm[];
    float* Vs  = sm;
    float* Ps  = Vs + 256 * VS_STRIDE;
    float* Qt  = Ps + 32 * PS_STRIDE;
    float* bsm = Qt + 32 * QT_STRIDE;

    const int tid = threadIdx.x;
    const int bh = blockIdx.x;
    const int b = bh >> 4;
    const int h = bh & 15;
    const size_t base = (size_t)bh * (S_ * DH_);

    for (int i = tid; i < 511; i += 256) bsm[i] = bias_table[i * H_ + h];

    {
        const float4* Vg = (const float4*)(g_v + base);
        #pragma unroll
        for (int it = 0; it < 8; it++) {
            int f = tid + it * 256;
            float4 v4 = Vg[f];
            int k = f >> 3;
            int u = (f & 7) << 2;
            float* p = &Vs[k * VS_STRIDE + u];
            p[0] = v4.x; p[1] = v4.y; p[2] = v4.z; p[3] = v4.w;
        }
    }

    float kreg[32];
    {
        const float4* Kg = (const float4*)(g_k + base + (size_t)tid * DH_);
        #pragma unroll
        for (int u = 0; u < 8; u++) {
            float4 k4 = Kg[u];
            kreg[u * 4 + 0] = k4.x; kreg[u * 4 + 1] = k4.y;
            kreg[u * 4 + 2] = k4.z; kreg[u * 4 + 3] = k4.w;
        }
    }
    __syncthreads();

    const float scale = 0.17677669529663687f;
    const int lane = tid & 31;
    const int warp = tid >> 5;
    const int ty = tid >> 4;
    const int tx = tid & 15;

    for (int qc = 0; qc < 8; qc++) {
        #pragma unroll
        for (int it = 0; it < 4; it++) {
            int e = tid + it * 256;
            int qq = e >> 5, d = e & 31;
            Qt[d * QT_STRIDE + qq] = g_q[base + (size_t)(qc * 32 + qq) * DH_ + d];
        }
        __syncthreads();

        {
            float acc[32];
            #pragma unroll
            for (int q = 0; q < 32; q++) acc[q] = 0.0f;
            #pragma unroll
            for (int d = 0; d < 32; d++) {
                const float kv = kreg[d];
                const float4* Qr = (const float4*)&Qt[d * QT_STRIDE];
                #pragma unroll
                for (int q4 = 0; q4 < 8; q4++) {
                    float4 qv = Qr[q4];
                    acc[q4 * 4 + 0] += kv * qv.x;
                    acc[q4 * 4 + 1] += kv * qv.y;
                    acc[q4 * 4 + 2] += kv * qv.z;
                    acc[q4 * 4 + 3] += kv * qv.w;
                }
            }
            #pragma unroll
            for (int q = 0; q < 32; q++)
                Ps[q * PS_STRIDE + tid] = acc[q] * scale;
        }
        __syncthreads();

        #pragma unroll
        for (int j = 0; j < 4; j++) {
            const int q = warp * 4 + j;
            const int qg = qc * 32 + q;
            float v[8];
            float mx = -1e30f;
            #pragma unroll
            for (int jj = 0; jj < 8; jj++) {
                v[jj] = Ps[q * PS_STRIDE + lane + jj * 32];
                mx = fmaxf(mx, v[jj]);
            }
            #pragma unroll
            for (int o = 16; o; o >>= 1) mx = fmaxf(mx, __shfl_xor_sync(0xffffffffu, mx, o));
            float sum = 0.0f;
            #pragma unroll
            for (int jj = 0; jj < 8; jj++) { v[jj] = expf(v[jj] - mx); sum += v[jj]; }
            #pragma unroll
            for (int o = 16; o; o >>= 1) sum += __shfl_xor_sync(0xffffffffu, sum, o);
            const float inv = 1.0f / sum;
            #pragma unroll
            for (int jj = 0; jj < 8; jj++) {
                const int k = lane + jj * 32;
                Ps[q * PS_STRIDE + k] = v[jj] * inv + bsm[qg - k + 255];
            }
        }
        __syncthreads();

        {
            float a00 = 0.f, a01 = 0.f, a10 = 0.f, a11 = 0.f;
            const float4* P0 = (const float4*)&Ps[(ty * 2 + 0) * PS_STRIDE];
            const float4* P1 = (const float4*)&Ps[(ty * 2 + 1) * PS_STRIDE];
            #pragma unroll
            for (int k4 = 0; k4 < 64; k4++) {
                float4 p0 = P0[k4];
                float4 p1 = P1[k4];
                const int k = k4 * 4;
                float2 w0 = *(const float2*)&Vs[(k + 0) * VS_STRIDE + tx * 2];
                float2 w1 = *(const float2*)&Vs[(k + 1) * VS_STRIDE + tx * 2];
                float2 w2 = *(const float2*)&Vs[(k + 2) * VS_STRIDE + tx * 2];
                float2 w3 = *(const float2*)&Vs[(k + 3) * VS_STRIDE + tx * 2];
                a00 += p0.x * w0.x; a01 += p0.x * w0.y; a10 += p1.x * w0.x; a11 += p1.x * w0.y;
                a00 += p0.y * w1.x; a01 += p0.y * w1.y; a10 += p1.y * w1.x; a11 += p1.y * w1.y;
                a00 += p0.z * w2.x; a01 += p0.z * w2.y; a10 += p1.z * w2.x; a11 += p1.z * w2.y;
                a00 += p0.w * w3.x; a01 += p0.w * w3.y; a10 += p1.w * w3.x; a11 += p1.w * w3.y;
            }
            const int qg = qc * 32 + ty * 2;
            float* o0 = &out[(size_t)(b * S_ + qg) * DIM_ + h * DH_ + tx * 2];
            *(float2*)o0          = make_float2(a00, a01);
            *(float2*)(o0 + DIM_) = make_float2(a10, a11);
        }
        __syncthreads();
    }
}

// ---------------------------------------------------------------------------
extern "C" void kernel_launch(void* const* d_in, const int* in_sizes, int n_in,
                              void* d_out, int out_size)
{
    const float* hs = (const float*)d_in[0];
    const float* Wq = (const float*)d_in[1];
    const float* bq = (const float*)d_in[2];
    const float* Wk = (const float*)d_in[3];
    const float* bk = (const float*)d_in[4];
    const float* Wv = (const float*)d_in[5];
    const float* bv = (const float*)d_in[6];
    const float* bias_table = (const float*)d_in[7];
    float* out = (float*)d_out;

    (void)in_sizes; (void)n_in; (void)out_size;

    cudaFuncSetAttribute(qkv_mma_kernel, cudaFuncAttributeMaxDynamicSharedMemorySize,
                         QS_TOTAL);
    cudaFuncSetAttribute(attn_kernel, cudaFuncAttributeMaxDynamicSharedMemorySize,
                         SMEM_FLOATS * (int)sizeof(float));

    prep_a_kernel<<<8192, 256>>>(hs);
    prep_w_kernel<<<dim3(16, 16, 3), 256>>>(Wq, Wk, Wv);
    qkv_mma_kernel<<<dim3(24, 128), 256, QS_TOTAL>>>(bq, bk, bv);
    attn_kernel<<<B_ * H_, 256, SMEM_FLOATS * sizeof(float)>>>(bias_table, out);
}

// round 9
// speedup vs baseline: 1.9034x; 1.3543x over previous
#include <cuda_runtime.h>
#include <cuda_bf16.h>
#include <math.h>
#include <stdint.h>

// Problem constants
#define B_   64
#define S_   256
#define DIM_ 512
#define H_   16
#define DH_  32
// -log2(10000)/32
#define ROPE_COEF (-0.41524101186092147f)

// ---------------------------------------------------------------------------
// Warp-level MMA helpers (sm_80+ features only; safe on target sm_103)
// ---------------------------------------------------------------------------
__device__ __forceinline__ uint32_t smem_to_u32(const void* smem_ptr) {
    uint32_t addr;
    asm("{ .reg .u64 tmp; cvta.to.shared.u64 tmp, %1; cvt.u32.u64 %0, tmp; }"
        : "=r"(addr) : "l"(smem_ptr));
    return addr;
}

__device__ __forceinline__ void ldm_x4(uint32_t* r, uint32_t addr) {
    asm volatile("ldmatrix.sync.aligned.m8n8.x4.shared.b16 {%0,%1,%2,%3}, [%4];"
                 : "=r"(r[0]), "=r"(r[1]), "=r"(r[2]), "=r"(r[3]) : "r"(addr));
}

__device__ __forceinline__ void ldm_x2t(uint32_t* r, uint32_t addr) {
    asm volatile("ldmatrix.sync.aligned.m8n8.x2.trans.shared.b16 {%0,%1}, [%2];"
                 : "=r"(r[0]), "=r"(r[1]) : "r"(addr));
}

__device__ __forceinline__ void mma16816(float* c, const uint32_t* a, const uint32_t* b) {
    asm volatile(
        "mma.sync.aligned.m16n8k16.row.col.f32.bf16.bf16.f32 "
        "{%0,%1,%2,%3}, {%4,%5,%6,%7}, {%8,%9}, {%0,%1,%2,%3};"
        : "+f"(c[0]), "+f"(c[1]), "+f"(c[2]), "+f"(c[3])
        : "r"(a[0]), "r"(a[1]), "r"(a[2]), "r"(a[3]), "r"(b[0]), "r"(b[1]));
}

__device__ __forceinline__ uint32_t pack_bf16(float x, float y) {
    __nv_bfloat162 p = __halves2bfloat162(__float2bfloat16(x), __float2bfloat16(y));
    return *(uint32_t*)&p;
}

// ---------------------------------------------------------------------------
// Scratch
// ---------------------------------------------------------------------------
// bf16 split of A (hidden states) [16384, 512]
__device__ __nv_bfloat16 g_ah[16384 * 512];
__device__ __nv_bfloat16 g_al[16384 * 512];
// bf16 split of W^T, all 3 matrices concatenated: rows = mat*512 + n, cols = k
__device__ __nv_bfloat16 g_wh[1536 * 512];
__device__ __nv_bfloat16 g_wl[1536 * 512];
// q/k/v in [B,H,S,DH], bf16 hi/lo pairs
#define QKV_ELEMS (B_ * H_ * S_ * DH_)
__device__ __nv_bfloat16 g_qh[QKV_ELEMS];
__device__ __nv_bfloat16 g_ql[QKV_ELEMS];
__device__ __nv_bfloat16 g_kh[QKV_ELEMS];
__device__ __nv_bfloat16 g_kl[QKV_ELEMS];
__device__ __nv_bfloat16 g_vh[QKV_ELEMS];
__device__ __nv_bfloat16 g_vl[QKV_ELEMS];

// ---------------------------------------------------------------------------
// Prep A: fp32 -> bf16 hi/lo split
// ---------------------------------------------------------------------------
__global__ __launch_bounds__(256) void prep_a_kernel(const float* __restrict__ hs) {
    size_t i = (size_t)blockIdx.x * 256 + threadIdx.x;   // float4 index
    float4 x = ((const float4*)hs)[i];
    __nv_bfloat16 h0 = __float2bfloat16(x.x);
    __nv_bfloat16 h1 = __float2bfloat16(x.y);
    __nv_bfloat16 h2 = __float2bfloat16(x.z);
    __nv_bfloat16 h3 = __float2bfloat16(x.w);
    __nv_bfloat16 l0 = __float2bfloat16(x.x - __bfloat162float(h0));
    __nv_bfloat16 l1 = __float2bfloat16(x.y - __bfloat162float(h1));
    __nv_bfloat16 l2 = __float2bfloat16(x.z - __bfloat162float(h2));
    __nv_bfloat16 l3 = __float2bfloat16(x.w - __bfloat162float(h3));
    __nv_bfloat162* AH2 = (__nv_bfloat162*)g_ah;
    __nv_bfloat162* AL2 = (__nv_bfloat162*)g_al;
    AH2[2 * i]     = __halves2bfloat162(h0, h1);
    AH2[2 * i + 1] = __halves2bfloat162(h2, h3);
    AL2[2 * i]     = __halves2bfloat162(l0, l1);
    AL2[2 * i + 1] = __halves2bfloat162(l2, l3);
}

// ---------------------------------------------------------------------------
// Prep W: transpose + bf16 hi/lo split.  WT[mat*512 + n][k] = W_mat[k][n]
// ---------------------------------------------------------------------------
__global__ __launch_bounds__(256) void prep_w_kernel(
    const float* __restrict__ Wq, const float* __restrict__ Wk, const float* __restrict__ Wv)
{
    __shared__ float t[32][33];
    const int tid = threadIdx.x;
    const int tx = tid & 31, ty = tid >> 5;
    const int mat = blockIdx.z;
    const float* W = (mat == 0) ? Wq : (mat == 1) ? Wk : Wv;
    const int n0 = blockIdx.x * 32, k0 = blockIdx.y * 32;

    #pragma unroll
    for (int j = 0; j < 4; j++) {
        int kk = ty + j * 8;
        t[kk][tx] = W[(size_t)(k0 + kk) * 512 + n0 + tx];
    }
    __syncthreads();
    #pragma unroll
    for (int j = 0; j < 4; j++) {
        int n = n0 + ty + j * 8;
        float v = t[tx][ty + j * 8];
        __nv_bfloat16 hi = __float2bfloat16(v);
        __nv_bfloat16 lo = __float2bfloat16(v - __bfloat162float(hi));
        size_t o = (size_t)(mat * 512 + n) * 512 + k0 + tx;
        g_wh[o] = hi;
        g_wl[o] = lo;
    }
}

// ---------------------------------------------------------------------------
// QKV GEMM via mma.sync bf16 (3-product hi/lo split) + bias + RoPE epilogue.
// Epilogue writes q/k/v as bf16 hi/lo into [B,H,S,DH].
// ---------------------------------------------------------------------------
#define QS_AH   0
#define QS_AL   10240
#define QS_BH   20480
#define QS_BL   25600
#define QS_BUF  30720
#define QS_TOTAL (2 * QS_BUF)   // 61440 bytes

__global__ __launch_bounds__(256) void qkv_mma_kernel(
    const float* __restrict__ bq, const float* __restrict__ bk, const float* __restrict__ bv)
{
    extern __shared__ char smem[];
    const uint32_t sb = smem_to_u32(smem);
    const int tid  = threadIdx.x;
    const int lane = tid & 31;
    const int warp = tid >> 5;
    const int wm = warp & 3;          // 0..3  (M)
    const int wn = warp >> 2;         // 0..1  (N)
    const int nbase = blockIdx.x * 64;     // 0..1472
    const int r0    = blockIdx.y * 128;
    const int mat   = nbase >> 9;
    const bool rope = (mat < 2);

    float acc[2][4][4];
    #pragma unroll
    for (int i = 0; i < 2; i++)
        #pragma unroll
        for (int j = 0; j < 4; j++)
            #pragma unroll
            for (int k = 0; k < 4; k++) acc[i][j][k] = 0.0f;

    const int grow = tid >> 2;            // 0..63
    const int gseg = (tid & 3) << 3;      // 0,8,16,24
    const size_t aSrc0 = (size_t)(r0 + grow) * 512 + gseg;
    const size_t aSrc1 = aSrc0 + (size_t)64 * 512;
    const size_t bSrc  = (size_t)(nbase + grow) * 512 + gseg;
    const uint32_t aDst0 = (uint32_t)(grow * 40 + gseg) * 2;
    const uint32_t aDst1 = (uint32_t)((grow + 64) * 40 + gseg) * 2;
    const uint32_t bDst  = aDst0;

    const uint32_t aLdmRow = (uint32_t)(lane & 15);
    const uint32_t aLdmCol = (uint32_t)((lane >> 4) << 3);
    const uint32_t bLdmRow = (uint32_t)((lane & 7) + (((lane >> 4) & 1) << 3));
    const uint32_t bLdmCol = (uint32_t)(((lane >> 3) & 1) << 3);

    {
        *(uint4*)(smem + QS_AH + aDst0) = *(const uint4*)&g_ah[aSrc0];
        *(uint4*)(smem + QS_AL + aDst0) = *(const uint4*)&g_al[aSrc0];
        *(uint4*)(smem + QS_AH + aDst1) = *(const uint4*)&g_ah[aSrc1];
        *(uint4*)(smem + QS_AL + aDst1) = *(const uint4*)&g_al[aSrc1];
        *(uint4*)(smem + QS_BH + bDst)  = *(const uint4*)&g_wh[bSrc];
        *(uint4*)(smem + QS_BL + bDst)  = *(const uint4*)&g_wl[bSrc];
    }
    __syncthreads();

    for (int c = 0; c < 16; c++) {
        uint4 pAh0, pAl0, pAh1, pAl1, pBh, pBl;
        if (c < 15) {
            const int kn = (c + 1) * 32;
            pAh0 = *(const uint4*)&g_ah[aSrc0 + kn];
            pAl0 = *(const uint4*)&g_al[aSrc0 + kn];
            pAh1 = *(const uint4*)&g_ah[aSrc1 + kn];
            pAl1 = *(const uint4*)&g_al[aSrc1 + kn];
            pBh  = *(const uint4*)&g_wh[bSrc + kn];
            pBl  = *(const uint4*)&g_wl[bSrc + kn];
        }

        const uint32_t bb = sb + (uint32_t)(c & 1) * QS_BUF;
        #pragma unroll
        for (int ks = 0; ks < 2; ks++) {
            uint32_t Ah[2][4], Al[2][4], Bh[2][4], Bl[2][4];
            #pragma unroll
            for (int mt = 0; mt < 2; mt++) {
                uint32_t eo = ((uint32_t)(wm * 32 + mt * 16) + aLdmRow) * 40
                              + (uint32_t)(ks * 16) + aLdmCol;
                ldm_x4(Ah[mt], bb + QS_AH + eo * 2);
                ldm_x4(Al[mt], bb + QS_AL + eo * 2);
            }
            #pragma unroll
            for (int p = 0; p < 2; p++) {
                uint32_t eo = ((uint32_t)(wn * 32 + p * 16) + bLdmRow) * 40
                              + (uint32_t)(ks * 16) + bLdmCol;
                ldm_x4(Bh[p], bb + QS_BH + eo * 2);
                ldm_x4(Bl[p], bb + QS_BL + eo * 2);
            }
            #pragma unroll
            for (int mt = 0; mt < 2; mt++)
                #pragma unroll
                for (int nt = 0; nt < 4; nt++) {
                    const uint32_t* bhp = &Bh[nt >> 1][(nt & 1) * 2];
                    const uint32_t* blp = &Bl[nt >> 1][(nt & 1) * 2];
                    mma16816(acc[mt][nt], Ah[mt], bhp);
                    mma16816(acc[mt][nt], Ah[mt], blp);
                    mma16816(acc[mt][nt], Al[mt], bhp);
                }
        }

        if (c < 15) {
            char* nb = smem + (size_t)((c + 1) & 1) * QS_BUF;
            *(uint4*)(nb + QS_AH + aDst0) = pAh0;
            *(uint4*)(nb + QS_AL + aDst0) = pAl0;
            *(uint4*)(nb + QS_AH + aDst1) = pAh1;
            *(uint4*)(nb + QS_AL + aDst1) = pAl1;
            *(uint4*)(nb + QS_BH + bDst)  = pBh;
            *(uint4*)(nb + QS_BL + bDst)  = pBl;
            __syncthreads();
        }
    }

    // Epilogue: bias + RoPE, write bf16 hi/lo [B,H,S,DH]
    const float* bias = (mat == 0) ? bq : (mat == 1) ? bk : bv;
    __nv_bfloat16* dh = (mat == 0) ? g_qh : (mat == 1) ? g_kh : g_vh;
    __nv_bfloat16* dl = (mat == 0) ? g_ql : (mat == 1) ? g_kl : g_vl;

    #pragma unroll
    for (int nt = 0; nt < 4; nt++) {
        const int cg = nbase + wn * 32 + nt * 8 + (lane & 3) * 2;  // global col
        const int cW = cg & 511;
        const int head = cW >> 5;
        const int d0 = cW & 31;                                    // even
        const float bi0 = bias[cW];
        const float bi1 = bias[cW + 1];
        const float ifr = rope ? exp2f((float)d0 * ROPE_COEF) : 0.0f;
        #pragma unroll
        for (int mt = 0; mt < 2; mt++) {
            const int rbase = r0 + wm * 32 + mt * 16 + (lane >> 2);
            #pragma unroll
            for (int half = 0; half < 2; half++) {
                const int r = rbase + half * 8;
                const int b = r >> 8;
                const int s = r & 255;
                float v0 = acc[mt][nt][half * 2 + 0] + bi0;
                float v1 = acc[mt][nt][half * 2 + 1] + bi1;
                if (rope) {
                    float sn, cs;
                    sincosf((float)s * ifr, &sn, &cs);
                    float t0 = v0 * cs - v1 * sn;
                    float t1 = v0 * sn + v1 * cs;
                    v0 = t0; v1 = t1;
                }
                __nv_bfloat16 h0 = __float2bfloat16(v0);
                __nv_bfloat16 h1 = __float2bfloat16(v1);
                float l0f = v0 - __bfloat162float(h0);
                float l1f = v1 - __bfloat162float(h1);
                size_t off = ((size_t)((b * H_ + head) * S_ + s) << 5) + d0;
                __nv_bfloat162 ph = __halves2bfloat162(h0, h1);
                __nv_bfloat162 pl = __halves2bfloat162(__float2bfloat16(l0f),
                                                       __float2bfloat16(l1f));
                *(__nv_bfloat162*)&dh[off] = ph;
                *(__nv_bfloat162*)&dl[off] = pl;
            }
        }
    }
}

// ---------------------------------------------------------------------------
// Attention via mma.sync. One block per (b,h), 256 threads = 8 warps.
// Per qc (32 q rows): S = QK^T (3-product hi/lo), softmax on fragments
// (quad shfl + cross-warp partials), P = softmax + bias -> hi/lo bf16 smem,
// ctx = P@V (3-product). Warp w owns k-cols [w*32, w*32+32) for S;
// for PV warp w owns tile (m = w&1, d = w>>1).
// ---------------------------------------------------------------------------
#define AS_KH 0
#define AS_KL 20480
#define AS_VH 40960
#define AS_VL 61440
#define AS_QH 81920
#define AS_QL 84480
#define AS_PH 87040
#define AS_PL 103936
#define AS_BI 120832
#define AS_MX 122880
#define AS_SM 124032
#define AS_TOTAL 125184

__global__ __launch_bounds__(256) void attn_mma_kernel(
    const float* __restrict__ bias_table, float* __restrict__ out)
{
    extern __shared__ char smem[];
    const uint32_t sb = smem_to_u32(smem);
    const int tid = threadIdx.x;
    const int lane = tid & 31;
    const int w = tid >> 5;
    const int grp = lane >> 2;
    const int tid4 = lane & 3;
    const int bh = blockIdx.x;
    const int b = bh >> 4;
    const int h = bh & 15;
    const size_t base = (size_t)bh * (S_ * DH_);

    float* bsm  = (float*)(smem + AS_BI);
    float* pmax = (float*)(smem + AS_MX);   // [32][9]
    float* psum = (float*)(smem + AS_SM);   // [32][9]

    for (int i = tid; i < 511; i += 256) bsm[i] = bias_table[i * H_ + h];

    // K/V -> smem, padded stride 40 bf16. Thread = one k-row.
    {
        const uint4* kh = (const uint4*)&g_kh[base + (size_t)tid * 32];
        const uint4* kl = (const uint4*)&g_kl[base + (size_t)tid * 32];
        const uint4* vh = (const uint4*)&g_vh[base + (size_t)tid * 32];
        const uint4* vl = (const uint4*)&g_vl[base + (size_t)tid * 32];
        uint4* dkh = (uint4*)(smem + AS_KH + tid * 80);
        uint4* dkl = (uint4*)(smem + AS_KL + tid * 80);
        uint4* dvh = (uint4*)(smem + AS_VH + tid * 80);
        uint4* dvl = (uint4*)(smem + AS_VL + tid * 80);
        #pragma unroll
        for (int j = 0; j < 4; j++) {
            dkh[j] = kh[j]; dkl[j] = kl[j];
            dvh[j] = vh[j]; dvl[j] = vl[j];
        }
    }

    // ldmatrix per-lane offsets
    const uint32_t a_row  = (uint32_t)(((lane >> 3) & 1) * 8 + (lane & 7));
    const uint32_t a_col8 = (uint32_t)(((lane >> 4) & 1) * 8);
    const uint32_t k_row  = (uint32_t)(((lane >> 4) & 1) * 8 + (lane & 7));
    const uint32_t k_col8 = (uint32_t)(((lane >> 3) & 1) * 8);
    const uint32_t v_row  = (uint32_t)(lane & 15);

    const int kb = w * 32;            // warp's k-row range for S
    const int wm = w & 1;             // PV m-tile
    const int wd = w >> 1;            // PV d-tile (n8)
    const float scale = 0.17677669529663687f;  // 1/sqrt(32)

    // Q-chunk load mapping: 4 bf16 per thread per array
    const int qrow_l = tid >> 3;            // 0..31
    const int qd     = (tid & 7) * 4;       // 0..28

    for (int qc = 0; qc < 8; qc++) {
        // Load Q chunk (hi/lo) into smem
        {
            size_t src = base + (size_t)(qc * 32 + qrow_l) * 32 + qd;
            uint32_t dst = (uint32_t)(qrow_l * 40 + qd) * 2;
            *(uint2*)(smem + AS_QH + dst) = *(const uint2*)&g_qh[src];
            *(uint2*)(smem + AS_QL + dst) = *(const uint2*)&g_ql[src];
        }
        __syncthreads();

        // ---- S = Q K^T (warp covers 32 q rows x its 32 k-cols) ----
        float acc[2][4][4];
        #pragma unroll
        for (int i = 0; i < 2; i++)
            #pragma unroll
            for (int j = 0; j < 4; j++)
                #pragma unroll
                for (int k2 = 0; k2 < 4; k2++) acc[i][j][k2] = 0.0f;

        #pragma unroll
        for (int ks = 0; ks < 2; ks++) {
            const uint32_t dbase = (uint32_t)(ks * 16);
            uint32_t Qh[2][4], Ql[2][4], Kh[2][4], Kl[2][4];
            #pragma unroll
            for (int mt = 0; mt < 2; mt++) {
                uint32_t eo = ((uint32_t)(mt * 16) + a_row) * 40 + dbase + a_col8;
                ldm_x4(Qh[mt], sb + AS_QH + eo * 2);
                ldm_x4(Ql[mt], sb + AS_QL + eo * 2);
            }
            #pragma unroll
            for (int rb = 0; rb < 2; rb++) {
                uint32_t eo = ((uint32_t)(kb + rb * 16) + k_row) * 40 + dbase + k_col8;
                ldm_x4(Kh[rb], sb + AS_KH + eo * 2);
                ldm_x4(Kl[rb], sb + AS_KL + eo * 2);
            }
            #pragma unroll
            for (int mt = 0; mt < 2; mt++)
                #pragma unroll
                for (int nt = 0; nt < 4; nt++) {
                    const uint32_t* bhp = &Kh[nt >> 1][(nt & 1) * 2];
                    const uint32_t* blp = &Kl[nt >> 1][(nt & 1) * 2];
                    mma16816(acc[mt][nt], Qh[mt], bhp);
                    mma16816(acc[mt][nt], Qh[mt], blp);
                    mma16816(acc[mt][nt], Ql[mt], bhp);
                }
        }

        // ---- softmax: row max ----
        float m0[2][2];
        #pragma unroll
        for (int mt = 0; mt < 2; mt++) {
            float ma = -1e30f, mb = -1e30f;
            #pragma unroll
            for (int nt = 0; nt < 4; nt++) {
                ma = fmaxf(ma, fmaxf(acc[mt][nt][0], acc[mt][nt][1]));
                mb = fmaxf(mb, fmaxf(acc[mt][nt][2], acc[mt][nt][3]));
            }
            m0[mt][0] = ma; m0[mt][1] = mb;
        }
        #pragma unroll
        for (int mt = 0; mt < 2; mt++)
            #pragma unroll
            for (int hf = 0; hf < 2; hf++) {
                float m = m0[mt][hf];
                m = fmaxf(m, __shfl_xor_sync(0xffffffffu, m, 1));
                m = fmaxf(m, __shfl_xor_sync(0xffffffffu, m, 2));
                m0[mt][hf] = m;
            }
        if (tid4 == 0) {
            #pragma unroll
            for (int mt = 0; mt < 2; mt++)
                #pragma unroll
                for (int hf = 0; hf < 2; hf++)
                    pmax[(mt * 16 + grp + hf * 8) * 9 + w] = m0[mt][hf];
        }
        __syncthreads();
        float fm[2][2];
        #pragma unroll
        for (int mt = 0; mt < 2; mt++)
            #pragma unroll
            for (int hf = 0; hf < 2; hf++) {
                const int row = mt * 16 + grp + hf * 8;
                float m = pmax[row * 9];
                #pragma unroll
                for (int j = 1; j < 8; j++) m = fmaxf(m, pmax[row * 9 + j]);
                fm[mt][hf] = m;
            }

        // ---- exp + row sum ----
        float s0[2][2] = {{0.f, 0.f}, {0.f, 0.f}};
        #pragma unroll
        for (int mt = 0; mt < 2; mt++)
            #pragma unroll
            for (int nt = 0; nt < 4; nt++) {
                acc[mt][nt][0] = __expf((acc[mt][nt][0] - fm[mt][0]) * scale);
                acc[mt][nt][1] = __expf((acc[mt][nt][1] - fm[mt][0]) * scale);
                acc[mt][nt][2] = __expf((acc[mt][nt][2] - fm[mt][1]) * scale);
                acc[mt][nt][3] = __expf((acc[mt][nt][3] - fm[mt][1]) * scale);
                s0[mt][0] += acc[mt][nt][0] + acc[mt][nt][1];
                s0[mt][1] += acc[mt][nt][2] + acc[mt][nt][3];
            }
        #pragma unroll
        for (int mt = 0; mt < 2; mt++)
            #pragma unroll
            for (int hf = 0; hf < 2; hf++) {
                float s = s0[mt][hf];
                s += __shfl_xor_sync(0xffffffffu, s, 1);
                s += __shfl_xor_sync(0xffffffffu, s, 2);
                s0[mt][hf] = s;
            }
        if (tid4 == 0) {
            #pragma unroll
            for (int mt = 0; mt < 2; mt++)
                #pragma unroll
                for (int hf = 0; hf < 2; hf++)
                    psum[(mt * 16 + grp + hf * 8) * 9 + w] = s0[mt][hf];
        }
        __syncthreads();
        float inv[2][2];
        #pragma unroll
        for (int mt = 0; mt < 2; mt++)
            #pragma unroll
            for (int hf = 0; hf < 2; hf++) {
                const int row = mt * 16 + grp + hf * 8;
                float s = psum[row * 9];
                #pragma unroll
                for (int j = 1; j < 8; j++) s += psum[row * 9 + j];
                inv[mt][hf] = 1.0f / s;
            }

        // ---- p = e*inv + bias; split hi/lo; store to Pb smem ----
        #pragma unroll
        for (int mt = 0; mt < 2; mt++)
            #pragma unroll
            for (int nt = 0; nt < 4; nt++) {
                const int kcol = kb + nt * 8 + tid4 * 2;
                const int r0g = qc * 32 + mt * 16 + grp;
                float p0 = acc[mt][nt][0] * inv[mt][0] + bsm[r0g - kcol + 255];
                float p1 = acc[mt][nt][1] * inv[mt][0] + bsm[r0g - kcol + 254];
                float p2 = acc[mt][nt][2] * inv[mt][1] + bsm[r0g + 8 - kcol + 255];
                float p3 = acc[mt][nt][3] * inv[mt][1] + bsm[r0g + 8 - kcol + 254];
                __nv_bfloat16 h0 = __float2bfloat16(p0);
                __nv_bfloat16 h1 = __float2bfloat16(p1);
                __nv_bfloat16 h2 = __float2bfloat16(p2);
                __nv_bfloat16 h3 = __float2bfloat16(p3);
                const int row0 = mt * 16 + grp;
                uint32_t o0 = (uint32_t)(row0 * 264 + kcol) * 2;
                uint32_t o1 = (uint32_t)((row0 + 8) * 264 + kcol) * 2;
                *(uint32_t*)(smem + AS_PH + o0) = pack_bf16(p0, p1);
                *(uint32_t*)(smem + AS_PH + o1) = pack_bf16(p2, p3);
                *(uint32_t*)(smem + AS_PL + o0) =
                    pack_bf16(p0 - __bfloat162float(h0), p1 - __bfloat162float(h1));
                *(uint32_t*)(smem + AS_PL + o1) =
                    pack_bf16(p2 - __bfloat162float(h2), p3 - __bfloat162float(h3));
            }
        __syncthreads();

        // ---- ctx = P @ V (warp tile: m = wm, n8 = wd), k = 256 ----
        float ctx[4] = {0.f, 0.f, 0.f, 0.f};
        #pragma unroll
        for (int ks = 0; ks < 16; ks++) {
            uint32_t Ph[4], Pl[4], Vh2[2], Vl2[2];
            uint32_t eoP = ((uint32_t)(wm * 16) + a_row) * 264 + (uint32_t)(ks * 16) + a_col8;
            ldm_x4(Ph, sb + AS_PH + eoP * 2);
            ldm_x4(Pl, sb + AS_PL + eoP * 2);
            uint32_t eoV = ((uint32_t)(ks * 16) + v_row) * 40 + (uint32_t)(wd * 8);
            ldm_x2t(Vh2, sb + AS_VH + eoV * 2);
            ldm_x2t(Vl2, sb + AS_VL + eoV * 2);
            mma16816(ctx, Ph, Vh2);
            mma16816(ctx, Ph, Vl2);
            mma16816(ctx, Pl, Vh2);
        }

        // ---- epilogue ----
        {
            const int qrow = qc * 32 + wm * 16 + grp;
            const int d = wd * 8 + tid4 * 2;
            float* o0 = &out[(size_t)(b * S_ + qrow) * DIM_ + h * DH_ + d];
            float* o1 = &out[(size_t)(b * S_ + qrow + 8) * DIM_ + h * DH_ + d];
            *(float2*)o0 = make_float2(ctx[0], ctx[1]);
            *(float2*)o1 = make_float2(ctx[2], ctx[3]);
        }
        __syncthreads();
    }
}

// ---------------------------------------------------------------------------
extern "C" void kernel_launch(void* const* d_in, const int* in_sizes, int n_in,
                              void* d_out, int out_size)
{
    const float* hs = (const float*)d_in[0];
    const float* Wq = (const float*)d_in[1];
    const float* bq = (const float*)d_in[2];
    const float* Wk = (const float*)d_in[3];
    const float* bk = (const float*)d_in[4];
    const float* Wv = (const float*)d_in[5];
    const float* bv = (const float*)d_in[6];
    const float* bias_table = (const float*)d_in[7];
    float* out = (float*)d_out;

    (void)in_sizes; (void)n_in; (void)out_size;

    cudaFuncSetAttribute(qkv_mma_kernel, cudaFuncAttributeMaxDynamicSharedMemorySize,
                         QS_TOTAL);
    cudaFuncSetAttribute(attn_mma_kernel, cudaFuncAttributeMaxDynamicSharedMemorySize,
                         AS_TOTAL);

    prep_a_kernel<<<8192, 256>>>(hs);
    prep_w_kernel<<<dim3(16, 16, 3), 256>>>(Wq, Wk, Wv);
    qkv_mma_kernel<<<dim3(24, 128), 256, QS_TOTAL>>>(bq, bk, bv);
    attn_mma_kernel<<<B_ * H_, 256, AS_TOTAL>>>(bias_table, out);
}